// round 8
// baseline (speedup 1.0000x reference)
#include <cuda_runtime.h>
#include <cuda_bf16.h>
#include <math.h>
#include <stdint.h>

#define BATCH 16
#define CCH   512
#define HH    64
#define WW    64
#define LWIN  256
#define NPOS  256
#define MTOT  65536
#define C3    1536
#define HEADS 8
#define DHEAD 64

typedef __nv_bfloat16 bf16;

// Pre-split bf16 hi/lo scratch
__device__ bf16 g_xh[(size_t)MTOT * CCH];
__device__ bf16 g_xl[(size_t)MTOT * CCH];
__device__ bf16 g_qh[(size_t)MTOT * C3];
__device__ bf16 g_ql[(size_t)MTOT * C3];
__device__ bf16 g_aoh[(size_t)MTOT * CCH];
__device__ bf16 g_aol[(size_t)MTOT * CCH];
__device__ bf16 g_wh[(size_t)C3 * CCH];
__device__ bf16 g_wl[(size_t)C3 * CCH];
__device__ bf16 g_owh[(size_t)CCH * CCH];
__device__ bf16 g_owl[(size_t)CCH * CCH];

// ---------------------------------------------------------------------------
// helpers
// ---------------------------------------------------------------------------
__device__ __forceinline__ void fsplit(float v, bf16& h, bf16& l) {
    h = __float2bfloat16_rn(v);
    l = __float2bfloat16_rn(v - __bfloat162float(h));
}
__device__ __forceinline__ uint32_t pack2(bf16 a, bf16 b) {
    return ((uint32_t)__bfloat16_as_ushort(b) << 16) | (uint32_t)__bfloat16_as_ushort(a);
}
__device__ __forceinline__ uint32_t cvta_s(const void* p) {
    return (uint32_t)__cvta_generic_to_shared(p);
}
__device__ __forceinline__ void cpa16(uint32_t d, const void* s) {
    asm volatile("cp.async.cg.shared.global [%0], [%1], 16;" :: "r"(d), "l"(s));
}
__device__ __forceinline__ void cp_commit() { asm volatile("cp.async.commit_group;"); }
__device__ __forceinline__ void cp_wait0()  { asm volatile("cp.async.wait_group 0;"); }
__device__ __forceinline__ void cp_wait1()  { asm volatile("cp.async.wait_group 1;"); }

__device__ __forceinline__ void ldsm4(uint32_t r[4], uint32_t a) {
    asm volatile("ldmatrix.sync.aligned.m8n8.x4.shared.b16 {%0,%1,%2,%3}, [%4];"
                 : "=r"(r[0]), "=r"(r[1]), "=r"(r[2]), "=r"(r[3]) : "r"(a));
}
__device__ __forceinline__ void ldsm4t(uint32_t r[4], uint32_t a) {
    asm volatile("ldmatrix.sync.aligned.m8n8.x4.trans.shared.b16 {%0,%1,%2,%3}, [%4];"
                 : "=r"(r[0]), "=r"(r[1]), "=r"(r[2]), "=r"(r[3]) : "r"(a));
}
__device__ __forceinline__ void mma16816(float c[4], const uint32_t a[4],
                                         uint32_t b0, uint32_t b1) {
    asm volatile(
        "mma.sync.aligned.m16n8k16.row.col.f32.bf16.bf16.f32 "
        "{%0,%1,%2,%3}, {%4,%5,%6,%7}, {%8,%9}, {%0,%1,%2,%3};"
        : "+f"(c[0]), "+f"(c[1]), "+f"(c[2]), "+f"(c[3])
        : "r"(a[0]), "r"(a[1]), "r"(a[2]), "r"(a[3]), "r"(b0), "r"(b1));
}

// ---------------------------------------------------------------------------
// Kernel: split weights into bf16 hi/lo
// ---------------------------------------------------------------------------
__global__ void split_weights_kernel(const float* __restrict__ w,
                                     const float* __restrict__ ow) {
    int i = blockIdx.x * blockDim.x + threadIdx.x;
    if (i < C3 * CCH)  fsplit(w[i],  g_wh[i],  g_wl[i]);
    if (i < CCH * CCH) fsplit(ow[i], g_owh[i], g_owl[i]);
}

// ---------------------------------------------------------------------------
// Kernel: layout transform x(B,C,H,W) -> split bf16 (m, c)
// ---------------------------------------------------------------------------
__global__ void rearrange_kernel(const float* __restrict__ x) {
    __shared__ float tile[32][33];
    int c0   = blockIdx.x * 32;
    int t    = blockIdx.y;
    int colt = t & 1;
    int row  = (t >> 1) & 63;
    int b    = t >> 7;
    int tx = threadIdx.x;
    int ty = threadIdx.y;

    #pragma unroll
    for (int r = 0; r < 4; r++) {
        int c   = c0 + ty + r * 8;
        int col = colt * 32 + tx;
        tile[ty + r * 8][tx] =
            x[(((size_t)b * CCH + c) * HH + row) * WW + col];
    }
    __syncthreads();

    int nh = row >> 4;
    int ii = row & 15;
    #pragma unroll
    for (int r = 0; r < 4; r++) {
        int col = colt * 32 + ty + r * 8;
        int nw  = col >> 4;
        int jj  = col & 15;
        int l   = b * 16 + nh * 4 + nw;
        int n_  = ii * 16 + jj;
        size_t m = (size_t)l * NPOS + n_;
        float v = tile[tx][ty + r * 8];
        bf16 hh, ll; fsplit(v, hh, ll);
        g_xh[m * CCH + c0 + tx] = hh;
        g_xl[m * CCH + c0 + tx] = ll;
    }
}

// ---------------------------------------------------------------------------
// Shared GEMM mainloop. C = A(128 rows) x B(128 rows)^T over K=512.
// 3-stage cp.async ring, ONE __syncthreads per K-iteration.
// Stage s at s*65536: Ah +0, Al +16384, Bh +32768, Bl +49152 (16KB each).
// ---------------------------------------------------------------------------
__device__ __forceinline__ void gemm_mainloop(
    const bf16* __restrict__ Ah, const bf16* __restrict__ Al,
    const bf16* __restrict__ Bh, const bf16* __restrict__ Bl,
    int m0, int n0, bf16* dsm, float acc[4][4][4]) {

    const int tid  = threadIdx.x;
    const int lane = tid & 31;
    const int wid  = tid >> 5;
    const int wm   = wid & 1;
    const int wn   = wid >> 1;

    const int sr  = tid >> 1;
    const int sc0 = (tid & 1) * 4;

    const bf16* gA0 = Ah + (size_t)(m0 + sr) * CCH;
    const bf16* gA1 = Al + (size_t)(m0 + sr) * CCH;
    const bf16* gB0 = Bh + (size_t)(n0 + sr) * CCH;
    const bf16* gB1 = Bl + (size_t)(n0 + sr) * CCH;

    uint32_t sbase = cvta_s(dsm);
    uint32_t rowoff = (uint32_t)(sr << 7);

    auto stage = [&](int it) {
        int kb = it * 64;
        uint32_t b = sbase + (uint32_t)(it % 3) * 65536u;
        const bf16* srcs[4] = { gA0 + kb, gA1 + kb, gB0 + kb, gB1 + kb };
        #pragma unroll
        for (int arr = 0; arr < 4; arr++) {
            uint32_t db = b + (uint32_t)arr * 16384u + rowoff;
            #pragma unroll
            for (int j = 0; j < 4; j++) {
                int c = sc0 + j;
                cpa16(db + (uint32_t)((c ^ (sr & 7)) << 4), srcs[arr] + c * 8);
            }
        }
    };

    auto compute = [&](int it) {
        uint32_t b  = sbase + (uint32_t)(it % 3) * 65536u;
        uint32_t aB = b;
        uint32_t bB = b + 32768u;
        #pragma unroll
        for (int ks = 0; ks < 4; ks++) {
            uint32_t aH[4][4], aL[4][4];
            #pragma unroll
            for (int mi = 0; mi < 4; mi++) {
                int row = wm * 64 + mi * 16 + (lane & 15);
                int cc  = 2 * ks + (lane >> 4);
                uint32_t off = (uint32_t)(row << 7) + (uint32_t)(((cc ^ (row & 7))) << 4);
                ldsm4(aH[mi], aB + off);
                ldsm4(aL[mi], aB + 16384u + off);
            }
            uint32_t bH[4][2], bL[4][2];
            #pragma unroll
            for (int p = 0; p < 2; p++) {
                int row = wn * 32 + p * 16 + ((lane >> 4) << 3) + (lane & 7);
                int cc  = 2 * ks + ((lane >> 3) & 1);
                uint32_t off = (uint32_t)(row << 7) + (uint32_t)(((cc ^ (row & 7))) << 4);
                uint32_t t4[4];
                ldsm4(t4, bB + off);
                bH[2*p][0] = t4[0]; bH[2*p][1] = t4[1];
                bH[2*p+1][0] = t4[2]; bH[2*p+1][1] = t4[3];
                ldsm4(t4, bB + 16384u + off);
                bL[2*p][0] = t4[0]; bL[2*p][1] = t4[1];
                bL[2*p+1][0] = t4[2]; bL[2*p+1][1] = t4[3];
            }
            #pragma unroll
            for (int mi = 0; mi < 4; mi++)
                #pragma unroll
                for (int nj = 0; nj < 4; nj++) {
                    mma16816(acc[mi][nj], aH[mi], bL[nj][0], bL[nj][1]);
                    mma16816(acc[mi][nj], aL[mi], bH[nj][0], bH[nj][1]);
                    mma16816(acc[mi][nj], aH[mi], bH[nj][0], bH[nj][1]);
                }
        }
    };

    // prologue: 2-deep prefetch
    stage(0); cp_commit();
    stage(1); cp_commit();
    for (int it = 0; it < 8; it++) {
        if (it < 7) cp_wait1(); else cp_wait0();
        __syncthreads();   // all warps done with buffer (it-1); group `it` visible
        if (it < 6) { stage(it + 2); cp_commit(); }  // ring slot (it+2)%3 is free
        compute(it);
    }
}

// QKV projection: writes split bf16 qkv (with bias, q pre-scaled by 1/8)
__global__ __launch_bounds__(256, 1) void gemm_qkv_tc(const float* __restrict__ bias) {
    extern __shared__ bf16 dsm[];
    int m0 = blockIdx.y * 128;
    int n0 = blockIdx.x * 128;
    float acc[4][4][4] = {};
    gemm_mainloop(g_xh, g_xl, g_wh, g_wl, m0, n0, dsm, acc);

    const int lane = threadIdx.x & 31, wid = threadIdx.x >> 5;
    const int wm = wid & 1, wn = wid >> 1;
    const int g = lane >> 2, q4 = lane & 3;
    #pragma unroll
    for (int mi = 0; mi < 4; mi++) {
        int r = m0 + wm * 64 + mi * 16 + g;
        #pragma unroll
        for (int nj = 0; nj < 4; nj++) {
            int c = n0 + wn * 32 + nj * 8 + q4 * 2;
            float sc = (c < CCH) ? 0.125f : 1.0f;
            float b0 = bias[c], b1 = bias[c + 1];
            float v00 = (acc[mi][nj][0] + b0) * sc;
            float v01 = (acc[mi][nj][1] + b1) * sc;
            float v10 = (acc[mi][nj][2] + b0) * sc;
            float v11 = (acc[mi][nj][3] + b1) * sc;
            bf16 ha, la, hb, lb;
            fsplit(v00, ha, la); fsplit(v01, hb, lb);
            *(uint32_t*)&g_qh[(size_t)r * C3 + c] = pack2(ha, hb);
            *(uint32_t*)&g_ql[(size_t)r * C3 + c] = pack2(la, lb);
            fsplit(v10, ha, la); fsplit(v11, hb, lb);
            *(uint32_t*)&g_qh[(size_t)(r + 8) * C3 + c] = pack2(ha, hb);
            *(uint32_t*)&g_ql[(size_t)(r + 8) * C3 + c] = pack2(la, lb);
        }
    }
}

__device__ __forceinline__ size_t spatial_index(int m, int c) {
    int l = m >> 8, n_ = m & 255;
    int b = l >> 4, rem = l & 15;
    int nh = rem >> 2, nw = rem & 3;
    int ii = n_ >> 4, jj = n_ & 15;
    int srow = nh * 16 + ii, scol = nw * 16 + jj;
    return (((size_t)b * CCH + c) * HH + srow) * WW + scol;
}

// Output projection + scatter to (B, C, H, W)
__global__ __launch_bounds__(256, 1) void gemm_out_tc(const float* __restrict__ bias,
                                                      float* __restrict__ Out) {
    extern __shared__ bf16 dsm[];
    int m0 = blockIdx.y * 128;
    int n0 = blockIdx.x * 128;
    float acc[4][4][4] = {};
    gemm_mainloop(g_aoh, g_aol, g_owh, g_owl, m0, n0, dsm, acc);

    const int lane = threadIdx.x & 31, wid = threadIdx.x >> 5;
    const int wm = wid & 1, wn = wid >> 1;
    const int g = lane >> 2, q4 = lane & 3;
    #pragma unroll
    for (int mi = 0; mi < 4; mi++) {
        int r = m0 + wm * 64 + mi * 16 + g;
        #pragma unroll
        for (int nj = 0; nj < 4; nj++) {
            int c = n0 + wn * 32 + nj * 8 + q4 * 2;
            float b0 = bias[c], b1 = bias[c + 1];
            Out[spatial_index(r, c)]         = acc[mi][nj][0] + b0;
            Out[spatial_index(r, c + 1)]     = acc[mi][nj][1] + b1;
            Out[spatial_index(r + 8, c)]     = acc[mi][nj][2] + b0;
            Out[spatial_index(r + 8, c + 1)] = acc[mi][nj][3] + b1;
        }
    }
}

// ---------------------------------------------------------------------------
// Tensor-core flash attention. One CTA per (n, h). FULLY-RESIDENT K/V:
// Qh@0 Ql@32768 Kh@65536 Kl@98304 Vh@131072 Vl@163840 (each 32KB = 256x128B).
// One load phase (cp.async), one barrier, then 4 key-chunks with NO barriers.
// ---------------------------------------------------------------------------
__global__ __launch_bounds__(256, 1) void attn_tc() {
    extern __shared__ bf16 dsm[];
    const int bx  = blockIdx.x;
    const int n   = bx & 255;
    const int h   = bx >> 8;
    const int tid = threadIdx.x;
    const int lane = tid & 31;
    const int wid  = tid >> 5;
    const int R0   = wid * 32;
    const int g = lane >> 2, q4 = lane & 3;

    uint32_t sbase = cvta_s(dsm);

    // ---- load Q + all of K, V (one row per thread per array) ----
    {
        size_t ro = ((size_t)tid * NPOS + n) * C3 + h * DHEAD;
        uint32_t rowo = (uint32_t)(tid << 7);
        #pragma unroll
        for (int j = 0; j < 8; j++) {
            uint32_t so = rowo + (uint32_t)((j ^ (tid & 7)) << 4);
            const bf16* qh = g_qh + ro + j * 8;
            const bf16* ql = g_ql + ro + j * 8;
            cpa16(sbase + so,            qh);          // Qh
            cpa16(sbase + 32768u  + so,  ql);          // Ql
            cpa16(sbase + 65536u  + so,  qh + 512);    // Kh
            cpa16(sbase + 98304u  + so,  ql + 512);    // Kl
            cpa16(sbase + 131072u + so,  qh + 1024);   // Vh
            cpa16(sbase + 163840u + so,  ql + 1024);   // Vl
        }
    }
    cp_commit();

    float o[2][8][4];
    #pragma unroll
    for (int mi = 0; mi < 2; mi++)
        #pragma unroll
        for (int nj = 0; nj < 8; nj++)
            #pragma unroll
            for (int i = 0; i < 4; i++) o[mi][nj][i] = 0.f;
    float ls[4] = {0.f, 0.f, 0.f, 0.f};

    cp_wait0();
    __syncthreads();   // the ONLY barrier before the epilogue

    const uint32_t qB = sbase;
    const uint32_t kB = sbase + 65536u;
    const uint32_t vB = sbase + 131072u;

    for (int ch = 0; ch < 4; ch++) {
        const int kr0 = ch * 64;   // first key row of this chunk

        // ---- S = Q K^T ----
        float s[2][8][4];
        #pragma unroll
        for (int mi = 0; mi < 2; mi++)
            #pragma unroll
            for (int nj = 0; nj < 8; nj++)
                #pragma unroll
                for (int i = 0; i < 4; i++) s[mi][nj][i] = 0.f;

        #pragma unroll
        for (int ks = 0; ks < 4; ks++) {
            uint32_t qh_[2][4], ql_[2][4];
            #pragma unroll
            for (int mi = 0; mi < 2; mi++) {
                int row = R0 + mi * 16 + (lane & 15);
                int cc  = 2 * ks + (lane >> 4);
                uint32_t off = (uint32_t)(row << 7) + (uint32_t)((cc ^ (row & 7)) << 4);
                ldsm4(qh_[mi], qB + off);
                ldsm4(ql_[mi], qB + 32768u + off);
            }
            uint32_t kh_[8][2], kl_[8][2];
            #pragma unroll
            for (int p = 0; p < 4; p++) {
                int row = kr0 + p * 16 + ((lane >> 4) << 3) + (lane & 7);
                int cc  = 2 * ks + ((lane >> 3) & 1);
                uint32_t off = (uint32_t)(row << 7) + (uint32_t)((cc ^ (row & 7)) << 4);
                uint32_t t4[4];
                ldsm4(t4, kB + off);
                kh_[2*p][0] = t4[0]; kh_[2*p][1] = t4[1];
                kh_[2*p+1][0] = t4[2]; kh_[2*p+1][1] = t4[3];
                ldsm4(t4, kB + 32768u + off);
                kl_[2*p][0] = t4[0]; kl_[2*p][1] = t4[1];
                kl_[2*p+1][0] = t4[2]; kl_[2*p+1][1] = t4[3];
            }
            #pragma unroll
            for (int mi = 0; mi < 2; mi++)
                #pragma unroll
                for (int nj = 0; nj < 8; nj++) {
                    mma16816(s[mi][nj], qh_[mi], kl_[nj][0], kl_[nj][1]);
                    mma16816(s[mi][nj], ql_[mi], kh_[nj][0], kh_[nj][1]);
                    mma16816(s[mi][nj], qh_[mi], kh_[nj][0], kh_[nj][1]);
                }
        }

        // ---- exp + row sums ----
        #pragma unroll
        for (int mi = 0; mi < 2; mi++)
            #pragma unroll
            for (int nj = 0; nj < 8; nj++)
                #pragma unroll
                for (int i = 0; i < 4; i++) {
                    float p = __expf(fminf(s[mi][nj][i], 25.f));
                    s[mi][nj][i] = p;
                    ls[2 * mi + (i >> 1)] += p;
                }

        // ---- O += P V ----
        #pragma unroll
        for (int ks = 0; ks < 4; ks++) {
            uint32_t ph_[2][4], pl_[2][4];
            #pragma unroll
            for (int mi = 0; mi < 2; mi++) {
                #pragma unroll
                for (int half = 0; half < 2; half++) {
                    int t = 2 * ks + half;
                    bf16 h0, l0, h1, l1;
                    // A-frag order: fill order IS the frag order — no reorder.
                    fsplit(s[mi][t][0], h0, l0); fsplit(s[mi][t][1], h1, l1);
                    ph_[mi][half * 2 + 0] = pack2(h0, h1);
                    pl_[mi][half * 2 + 0] = pack2(l0, l1);
                    fsplit(s[mi][t][2], h0, l0); fsplit(s[mi][t][3], h1, l1);
                    ph_[mi][half * 2 + 1] = pack2(h0, h1);
                    pl_[mi][half * 2 + 1] = pack2(l0, l1);
                }
            }
            uint32_t vh_[8][2], vl_[8][2];
            #pragma unroll
            for (int p = 0; p < 4; p++) {
                int row = kr0 + 16 * ks + ((lane >> 3) & 1) * 8 + (lane & 7);
                int cc  = 2 * p + (lane >> 4);
                uint32_t off = (uint32_t)(row << 7) + (uint32_t)((cc ^ (row & 7)) << 4);
                uint32_t t4[4];
                ldsm4t(t4, vB + off);
                vh_[2*p][0] = t4[0]; vh_[2*p][1] = t4[1];
                vh_[2*p+1][0] = t4[2]; vh_[2*p+1][1] = t4[3];
                ldsm4t(t4, vB + 32768u + off);
                vl_[2*p][0] = t4[0]; vl_[2*p][1] = t4[1];
                vl_[2*p+1][0] = t4[2]; vl_[2*p+1][1] = t4[3];
            }
            #pragma unroll
            for (int mi = 0; mi < 2; mi++)
                #pragma unroll
                for (int nj = 0; nj < 8; nj++) {
                    mma16816(o[mi][nj], ph_[mi], vl_[nj][0], vl_[nj][1]);
                    mma16816(o[mi][nj], pl_[mi], vh_[nj][0], vh_[nj][1]);
                    mma16816(o[mi][nj], ph_[mi], vh_[nj][0], vh_[nj][1]);
                }
        }
    }

    // ---- normalize + write split bf16 output ----
    #pragma unroll
    for (int i = 0; i < 4; i++) {
        ls[i] += __shfl_xor_sync(0xffffffffu, ls[i], 1);
        ls[i] += __shfl_xor_sync(0xffffffffu, ls[i], 2);
        ls[i] = 1.f / ls[i];
    }
    #pragma unroll
    for (int mi = 0; mi < 2; mi++) {
        int r0 = R0 + mi * 16 + g;
        #pragma unroll
        for (int nj = 0; nj < 8; nj++) {
            int c = h * DHEAD + nj * 8 + q4 * 2;
            float v00 = o[mi][nj][0] * ls[2*mi],     v01 = o[mi][nj][1] * ls[2*mi];
            float v10 = o[mi][nj][2] * ls[2*mi + 1], v11 = o[mi][nj][3] * ls[2*mi + 1];
            bf16 ha, la, hb, lb;
            size_t a0 = ((size_t)r0 * NPOS + n) * CCH + c;
            fsplit(v00, ha, la); fsplit(v01, hb, lb);
            *(uint32_t*)&g_aoh[a0] = pack2(ha, hb);
            *(uint32_t*)&g_aol[a0] = pack2(la, lb);
            size_t a1 = ((size_t)(r0 + 8) * NPOS + n) * CCH + c;
            fsplit(v10, ha, la); fsplit(v11, hb, lb);
            *(uint32_t*)&g_aoh[a1] = pack2(ha, hb);
            *(uint32_t*)&g_aol[a1] = pack2(la, lb);
        }
    }
}

// ---------------------------------------------------------------------------
extern "C" void kernel_launch(void* const* d_in, const int* in_sizes, int n_in,
                              void* d_out, int out_size) {
    const float* x         = (const float*)d_in[0];
    const float* in_proj_w = (const float*)d_in[1];
    const float* in_proj_b = (const float*)d_in[2];
    const float* out_w     = (const float*)d_in[3];
    const float* out_b     = (const float*)d_in[4];
    float* out = (float*)d_out;

    cudaFuncSetAttribute(gemm_qkv_tc, cudaFuncAttributeMaxDynamicSharedMemorySize, 196608);
    cudaFuncSetAttribute(gemm_out_tc, cudaFuncAttributeMaxDynamicSharedMemorySize, 196608);
    cudaFuncSetAttribute(attn_tc,     cudaFuncAttributeMaxDynamicSharedMemorySize, 196608);

    split_weights_kernel<<<(C3 * CCH + 255) / 256, 256>>>(in_proj_w, out_w);
    {
        dim3 grid(CCH / 32, BATCH * HH * 2);
        dim3 blk(32, 8);
        rearrange_kernel<<<grid, blk>>>(x);
    }
    {
        dim3 grid(C3 / 128, MTOT / 128);
        gemm_qkv_tc<<<grid, 256, 196608>>>(in_proj_b);
    }
    attn_tc<<<NPOS * HEADS, 256, 196608>>>();
    {
        dim3 grid(CCH / 128, MTOT / 128);
        gemm_out_tc<<<grid, 256, 196608>>>(out_b, out);
    }
}

// round 11
// speedup vs baseline: 1.1341x; 1.1341x over previous
#include <cuda_runtime.h>
#include <cuda_bf16.h>
#include <math.h>
#include <stdint.h>

#define BATCH 16
#define CCH   512
#define HH    64
#define WW    64
#define LWIN  256
#define NPOS  256
#define MTOT  65536
#define C3    1536
#define HEADS 8
#define DHEAD 64

typedef __nv_bfloat16 bf16;

// Pre-split bf16 hi/lo scratch
__device__ bf16 g_xh[(size_t)MTOT * CCH];
__device__ bf16 g_xl[(size_t)MTOT * CCH];
__device__ bf16 g_qh[(size_t)MTOT * C3];
__device__ bf16 g_ql[(size_t)MTOT * C3];
__device__ bf16 g_aoh[(size_t)MTOT * CCH];
__device__ bf16 g_aol[(size_t)MTOT * CCH];
__device__ bf16 g_wh[(size_t)C3 * CCH];
__device__ bf16 g_wl[(size_t)C3 * CCH];
__device__ bf16 g_owh[(size_t)CCH * CCH];
__device__ bf16 g_owl[(size_t)CCH * CCH];

// ---------------------------------------------------------------------------
// helpers
// ---------------------------------------------------------------------------
__device__ __forceinline__ void fsplit(float v, bf16& h, bf16& l) {
    h = __float2bfloat16_rn(v);
    l = __float2bfloat16_rn(v - __bfloat162float(h));
}
__device__ __forceinline__ uint32_t pack2(bf16 a, bf16 b) {
    return ((uint32_t)__bfloat16_as_ushort(b) << 16) | (uint32_t)__bfloat16_as_ushort(a);
}
__device__ __forceinline__ uint32_t cvta_s(const void* p) {
    return (uint32_t)__cvta_generic_to_shared(p);
}
__device__ __forceinline__ void cpa16(uint32_t d, const void* s) {
    asm volatile("cp.async.cg.shared.global [%0], [%1], 16;" :: "r"(d), "l"(s));
}
__device__ __forceinline__ void cp_commit() { asm volatile("cp.async.commit_group;"); }
__device__ __forceinline__ void cp_wait0()  { asm volatile("cp.async.wait_group 0;"); }
__device__ __forceinline__ void cp_wait1()  { asm volatile("cp.async.wait_group 1;"); }

__device__ __forceinline__ void ldsm4(uint32_t r[4], uint32_t a) {
    asm volatile("ldmatrix.sync.aligned.m8n8.x4.shared.b16 {%0,%1,%2,%3}, [%4];"
                 : "=r"(r[0]), "=r"(r[1]), "=r"(r[2]), "=r"(r[3]) : "r"(a));
}
__device__ __forceinline__ void ldsm4t(uint32_t r[4], uint32_t a) {
    asm volatile("ldmatrix.sync.aligned.m8n8.x4.trans.shared.b16 {%0,%1,%2,%3}, [%4];"
                 : "=r"(r[0]), "=r"(r[1]), "=r"(r[2]), "=r"(r[3]) : "r"(a));
}
__device__ __forceinline__ void mma16816(float c[4], const uint32_t a[4],
                                         uint32_t b0, uint32_t b1) {
    asm volatile(
        "mma.sync.aligned.m16n8k16.row.col.f32.bf16.bf16.f32 "
        "{%0,%1,%2,%3}, {%4,%5,%6,%7}, {%8,%9}, {%0,%1,%2,%3};"
        : "+f"(c[0]), "+f"(c[1]), "+f"(c[2]), "+f"(c[3])
        : "r"(a[0]), "r"(a[1]), "r"(a[2]), "r"(a[3]), "r"(b0), "r"(b1));
}

// ---------------------------------------------------------------------------
// Kernel: split weights into bf16 hi/lo
// ---------------------------------------------------------------------------
__global__ void split_weights_kernel(const float* __restrict__ w,
                                     const float* __restrict__ ow) {
    int i = blockIdx.x * blockDim.x + threadIdx.x;
    if (i < C3 * CCH)  fsplit(w[i],  g_wh[i],  g_wl[i]);
    if (i < CCH * CCH) fsplit(ow[i], g_owh[i], g_owl[i]);
}

// ---------------------------------------------------------------------------
// Kernel: layout transform x(B,C,H,W) -> split bf16 (m, c)
// ---------------------------------------------------------------------------
__global__ void rearrange_kernel(const float* __restrict__ x) {
    __shared__ float tile[32][33];
    int c0   = blockIdx.x * 32;
    int t    = blockIdx.y;
    int colt = t & 1;
    int row  = (t >> 1) & 63;
    int b    = t >> 7;
    int tx = threadIdx.x;
    int ty = threadIdx.y;

    #pragma unroll
    for (int r = 0; r < 4; r++) {
        int c   = c0 + ty + r * 8;
        int col = colt * 32 + tx;
        tile[ty + r * 8][tx] =
            x[(((size_t)b * CCH + c) * HH + row) * WW + col];
    }
    __syncthreads();

    int nh = row >> 4;
    int ii = row & 15;
    #pragma unroll
    for (int r = 0; r < 4; r++) {
        int col = colt * 32 + ty + r * 8;
        int nw  = col >> 4;
        int jj  = col & 15;
        int l   = b * 16 + nh * 4 + nw;
        int n_  = ii * 16 + jj;
        size_t m = (size_t)l * NPOS + n_;
        float v = tile[tx][ty + r * 8];
        bf16 hh, ll; fsplit(v, hh, ll);
        g_xh[m * CCH + c0 + tx] = hh;
        g_xl[m * CCH + c0 + tx] = ll;
    }
}

// ---------------------------------------------------------------------------
// GEMM mainloop, BM=64 x BN=128, K=512 in 8 blocks of 64.
// 2-stage ring of 48KB stages (96KB total) -> 2 CTAs/SM.
// Stage s at s*49152: Ah +0 (8KB), Al +8192, Bh +16384 (16KB), Bl +32768.
// Ordering per iter: wait(all) -> syncthreads -> stage(it+1) -> compute(it).
// stage(it+1) is AFTER the barrier, so buffer reuse is hazard-free with one sync.
// ---------------------------------------------------------------------------
__device__ __forceinline__ void gemm_mainloop(
    const bf16* __restrict__ Ah, const bf16* __restrict__ Al,
    const bf16* __restrict__ Bh, const bf16* __restrict__ Bl,
    int m0, int n0, bf16* dsm, float acc[2][4][4]) {

    const int tid  = threadIdx.x;
    const int lane = tid & 31;
    const int wid  = tid >> 5;
    const int wm   = wid & 1;    // 2 m-warps (32 rows each)
    const int wn   = wid >> 1;   // 4 n-warps (32 cols each)

    // staging maps: A = 64 rows x 8 chunks (2/thread), B = 128 rows x 8 (4/thread)
    const int ar  = tid >> 2;          // 0..63
    const int ac0 = (tid & 3) * 2;     // 0,2,4,6
    const int br  = tid >> 1;          // 0..127
    const int bc0 = (tid & 1) * 4;     // 0,4

    const bf16* gAh = Ah + (size_t)(m0 + ar) * CCH;
    const bf16* gAl = Al + (size_t)(m0 + ar) * CCH;
    const bf16* gBh = Bh + (size_t)(n0 + br) * CCH;
    const bf16* gBl = Bl + (size_t)(n0 + br) * CCH;

    uint32_t sbase = cvta_s(dsm);
    const uint32_t arow = (uint32_t)(ar << 7);
    const uint32_t brow = (uint32_t)(br << 7);

    auto stage = [&](int it) {
        int kb = it * 64;
        uint32_t b = sbase + (uint32_t)(it & 1) * 49152u;
        #pragma unroll
        for (int j = 0; j < 2; j++) {
            int c = ac0 + j;
            uint32_t so = arow + (uint32_t)((c ^ (ar & 7)) << 4);
            cpa16(b + so,          gAh + kb + c * 8);
            cpa16(b + 8192u + so,  gAl + kb + c * 8);
        }
        #pragma unroll
        for (int j = 0; j < 4; j++) {
            int c = bc0 + j;
            uint32_t so = brow + (uint32_t)((c ^ (br & 7)) << 4);
            cpa16(b + 16384u + so, gBh + kb + c * 8);
            cpa16(b + 32768u + so, gBl + kb + c * 8);
        }
    };

    auto compute = [&](int it) {
        uint32_t b  = sbase + (uint32_t)(it & 1) * 49152u;
        uint32_t aB = b;
        uint32_t bB = b + 16384u;
        #pragma unroll
        for (int ks = 0; ks < 4; ks++) {
            uint32_t aH[2][4], aL[2][4];
            #pragma unroll
            for (int mi = 0; mi < 2; mi++) {
                int row = wm * 32 + mi * 16 + (lane & 15);
                int cc  = 2 * ks + (lane >> 4);
                uint32_t off = (uint32_t)(row << 7) + (uint32_t)(((cc ^ (row & 7))) << 4);
                ldsm4(aH[mi], aB + off);
                ldsm4(aL[mi], aB + 8192u + off);
            }
            uint32_t bH[4][2], bL[4][2];
            #pragma unroll
            for (int p = 0; p < 2; p++) {
                int row = wn * 32 + p * 16 + ((lane >> 4) << 3) + (lane & 7);
                int cc  = 2 * ks + ((lane >> 3) & 1);
                uint32_t off = (uint32_t)(row << 7) + (uint32_t)(((cc ^ (row & 7))) << 4);
                uint32_t t4[4];
                ldsm4(t4, bB + off);
                bH[2*p][0] = t4[0]; bH[2*p][1] = t4[1];
                bH[2*p+1][0] = t4[2]; bH[2*p+1][1] = t4[3];
                ldsm4(t4, bB + 16384u + off);
                bL[2*p][0] = t4[0]; bL[2*p][1] = t4[1];
                bL[2*p+1][0] = t4[2]; bL[2*p+1][1] = t4[3];
            }
            #pragma unroll
            for (int mi = 0; mi < 2; mi++)
                #pragma unroll
                for (int nj = 0; nj < 4; nj++) {
                    mma16816(acc[mi][nj], aH[mi], bL[nj][0], bL[nj][1]);
                    mma16816(acc[mi][nj], aL[mi], bH[nj][0], bH[nj][1]);
                    mma16816(acc[mi][nj], aH[mi], bH[nj][0], bH[nj][1]);
                }
        }
    };

    stage(0); cp_commit();
    for (int it = 0; it < 8; it++) {
        cp_wait0();          // group 'it' (committed last iter) complete
        __syncthreads();     // all warps done with compute(it-1), data visible
        if (it < 7) { stage(it + 1); cp_commit(); }
        compute(it);
    }
}

// QKV projection: writes split bf16 qkv (with bias, q pre-scaled by 1/8)
__global__ __launch_bounds__(256, 2) void gemm_qkv_tc(const float* __restrict__ bias) {
    extern __shared__ bf16 dsm[];
    int m0 = blockIdx.y * 64;
    int n0 = blockIdx.x * 128;
    float acc[2][4][4] = {};
    gemm_mainloop(g_xh, g_xl, g_wh, g_wl, m0, n0, dsm, acc);

    const int lane = threadIdx.x & 31, wid = threadIdx.x >> 5;
    const int wm = wid & 1, wn = wid >> 1;
    const int g = lane >> 2, q4 = lane & 3;
    #pragma unroll
    for (int mi = 0; mi < 2; mi++) {
        int r = m0 + wm * 32 + mi * 16 + g;
        #pragma unroll
        for (int nj = 0; nj < 4; nj++) {
            int c = n0 + wn * 32 + nj * 8 + q4 * 2;
            float sc = (c < CCH) ? 0.125f : 1.0f;
            float b0 = bias[c], b1 = bias[c + 1];
            float v00 = (acc[mi][nj][0] + b0) * sc;
            float v01 = (acc[mi][nj][1] + b1) * sc;
            float v10 = (acc[mi][nj][2] + b0) * sc;
            float v11 = (acc[mi][nj][3] + b1) * sc;
            bf16 ha, la, hb, lb;
            fsplit(v00, ha, la); fsplit(v01, hb, lb);
            *(uint32_t*)&g_qh[(size_t)r * C3 + c] = pack2(ha, hb);
            *(uint32_t*)&g_ql[(size_t)r * C3 + c] = pack2(la, lb);
            fsplit(v10, ha, la); fsplit(v11, hb, lb);
            *(uint32_t*)&g_qh[(size_t)(r + 8) * C3 + c] = pack2(ha, hb);
            *(uint32_t*)&g_ql[(size_t)(r + 8) * C3 + c] = pack2(la, lb);
        }
    }
}

__device__ __forceinline__ size_t spatial_index(int m, int c) {
    int l = m >> 8, n_ = m & 255;
    int b = l >> 4, rem = l & 15;
    int nh = rem >> 2, nw = rem & 3;
    int ii = n_ >> 4, jj = n_ & 15;
    int srow = nh * 16 + ii, scol = nw * 16 + jj;
    return (((size_t)b * CCH + c) * HH + srow) * WW + scol;
}

// Output projection + scatter to (B, C, H, W)
__global__ __launch_bounds__(256, 2) void gemm_out_tc(const float* __restrict__ bias,
                                                      float* __restrict__ Out) {
    extern __shared__ bf16 dsm[];
    int m0 = blockIdx.y * 64;
    int n0 = blockIdx.x * 128;
    float acc[2][4][4] = {};
    gemm_mainloop(g_aoh, g_aol, g_owh, g_owl, m0, n0, dsm, acc);

    const int lane = threadIdx.x & 31, wid = threadIdx.x >> 5;
    const int wm = wid & 1, wn = wid >> 1;
    const int g = lane >> 2, q4 = lane & 3;
    #pragma unroll
    for (int mi = 0; mi < 2; mi++) {
        int r = m0 + wm * 32 + mi * 16 + g;
        #pragma unroll
        for (int nj = 0; nj < 4; nj++) {
            int c = n0 + wn * 32 + nj * 8 + q4 * 2;
            float b0 = bias[c], b1 = bias[c + 1];
            Out[spatial_index(r, c)]         = acc[mi][nj][0] + b0;
            Out[spatial_index(r, c + 1)]     = acc[mi][nj][1] + b1;
            Out[spatial_index(r + 8, c)]     = acc[mi][nj][2] + b0;
            Out[spatial_index(r + 8, c + 1)] = acc[mi][nj][3] + b1;
        }
    }
}

// ---------------------------------------------------------------------------
// Tensor-core flash attention (R7 proven version, 371us). One CTA per (n, h).
// KV in 4 chunks of 64 keys, cp.async double-buffered. smem 128KB.
// ---------------------------------------------------------------------------
__global__ __launch_bounds__(256, 1) void attn_tc() {
    extern __shared__ bf16 dsm[];
    const int bx  = blockIdx.x;
    const int n   = bx & 255;
    const int h   = bx >> 8;
    const int tid = threadIdx.x;
    const int lane = tid & 31;
    const int wid  = tid >> 5;
    const int R0   = wid * 32;
    const int g = lane >> 2, q4 = lane & 3;

    uint32_t sbase = cvta_s(dsm);

    // ---- load Q ----
    {
        size_t ro = ((size_t)tid * NPOS + n) * C3 + h * DHEAD;
        uint32_t dH = sbase + (uint32_t)(tid << 7);
        uint32_t dL = sbase + 32768u + (uint32_t)(tid << 7);
        #pragma unroll
        for (int j = 0; j < 8; j++) {
            uint32_t so = (uint32_t)((j ^ (tid & 7)) << 4);
            cpa16(dH + so, g_qh + ro + j * 8);
            cpa16(dL + so, g_ql + ro + j * 8);
        }
    }
    cp_commit();

    auto load_kv = [&](int ch, int b) {
        int k0 = ch * 64;
        uint32_t kvb = sbase + 65536u + (uint32_t)b * 32768u;
        #pragma unroll
        for (int j = 0; j < 2; j++) {
            int id = tid * 2 + j;
            int r = id >> 3, c = id & 7;
            size_t gro = ((size_t)(k0 + r) * NPOS + n) * C3 + h * DHEAD + c * 8;
            uint32_t dst = (uint32_t)(r << 7) + (uint32_t)((c ^ (r & 7)) << 4);
            cpa16(kvb + dst,          g_qh + gro + 512);   // Kh
            cpa16(kvb + 8192u + dst,  g_ql + gro + 512);   // Kl
            cpa16(kvb + 16384u + dst, g_qh + gro + 1024);  // Vh
            cpa16(kvb + 24576u + dst, g_ql + gro + 1024);  // Vl
        }
    };

    load_kv(0, 0); cp_commit();

    float o[2][8][4];
    #pragma unroll
    for (int mi = 0; mi < 2; mi++)
        #pragma unroll
        for (int nj = 0; nj < 8; nj++)
            #pragma unroll
            for (int i = 0; i < 4; i++) o[mi][nj][i] = 0.f;
    float ls[4] = {0.f, 0.f, 0.f, 0.f};

    for (int ch = 0; ch < 4; ch++) {
        if (ch < 3) { load_kv(ch + 1, (ch + 1) & 1); cp_commit(); cp_wait1(); }
        else        { cp_wait0(); }
        __syncthreads();

        uint32_t kB = sbase + 65536u + (uint32_t)(ch & 1) * 32768u;
        uint32_t vB = kB + 16384u;

        // ---- S = Q K^T ----
        float s[2][8][4];
        #pragma unroll
        for (int mi = 0; mi < 2; mi++)
            #pragma unroll
            for (int nj = 0; nj < 8; nj++)
                #pragma unroll
                for (int i = 0; i < 4; i++) s[mi][nj][i] = 0.f;

        #pragma unroll
        for (int ks = 0; ks < 4; ks++) {
            uint32_t qh_[2][4], ql_[2][4];
            #pragma unroll
            for (int mi = 0; mi < 2; mi++) {
                int row = R0 + mi * 16 + (lane & 15);
                int cc  = 2 * ks + (lane >> 4);
                uint32_t off = (uint32_t)(row << 7) + (uint32_t)((cc ^ (row & 7)) << 4);
                ldsm4(qh_[mi], sbase + off);
                ldsm4(ql_[mi], sbase + 32768u + off);
            }
            uint32_t kh_[8][2], kl_[8][2];
            #pragma unroll
            for (int p = 0; p < 4; p++) {
                int row = p * 16 + ((lane >> 4) << 3) + (lane & 7);
                int cc  = 2 * ks + ((lane >> 3) & 1);
                uint32_t off = (uint32_t)(row << 7) + (uint32_t)((cc ^ (row & 7)) << 4);
                uint32_t t4[4];
                ldsm4(t4, kB + off);
                kh_[2*p][0] = t4[0]; kh_[2*p][1] = t4[1];
                kh_[2*p+1][0] = t4[2]; kh_[2*p+1][1] = t4[3];
                ldsm4(t4, kB + 8192u + off);
                kl_[2*p][0] = t4[0]; kl_[2*p][1] = t4[1];
                kl_[2*p+1][0] = t4[2]; kl_[2*p+1][1] = t4[3];
            }
            #pragma unroll
            for (int mi = 0; mi < 2; mi++)
                #pragma unroll
                for (int nj = 0; nj < 8; nj++) {
                    mma16816(s[mi][nj], qh_[mi], kl_[nj][0], kl_[nj][1]);
                    mma16816(s[mi][nj], ql_[mi], kh_[nj][0], kh_[nj][1]);
                    mma16816(s[mi][nj], qh_[mi], kh_[nj][0], kh_[nj][1]);
                }
        }

        // ---- exp + row sums ----
        #pragma unroll
        for (int mi = 0; mi < 2; mi++)
            #pragma unroll
            for (int nj = 0; nj < 8; nj++)
                #pragma unroll
                for (int i = 0; i < 4; i++) {
                    float p = __expf(fminf(s[mi][nj][i], 25.f));
                    s[mi][nj][i] = p;
                    ls[2 * mi + (i >> 1)] += p;
                }

        // ---- O += P V ----
        #pragma unroll
        for (int ks = 0; ks < 4; ks++) {
            uint32_t ph_[2][4], pl_[2][4];
            #pragma unroll
            for (int mi = 0; mi < 2; mi++) {
                #pragma unroll
                for (int half = 0; half < 2; half++) {
                    int t = 2 * ks + half;
                    bf16 h0, l0, h1, l1;
                    fsplit(s[mi][t][0], h0, l0); fsplit(s[mi][t][1], h1, l1);
                    ph_[mi][half * 2 + 0] = pack2(h0, h1);
                    pl_[mi][half * 2 + 0] = pack2(l0, l1);
                    fsplit(s[mi][t][2], h0, l0); fsplit(s[mi][t][3], h1, l1);
                    ph_[mi][half * 2 + 1] = pack2(h0, h1);
                    pl_[mi][half * 2 + 1] = pack2(l0, l1);
                }
            }
            uint32_t vh_[8][2], vl_[8][2];
            #pragma unroll
            for (int p = 0; p < 4; p++) {
                int row = 16 * ks + ((lane >> 3) & 1) * 8 + (lane & 7);
                int cc  = 2 * p + (lane >> 4);
                uint32_t off = (uint32_t)(row << 7) + (uint32_t)((cc ^ (row & 7)) << 4);
                uint32_t t4[4];
                ldsm4t(t4, vB + off);
                vh_[2*p][0] = t4[0]; vh_[2*p][1] = t4[1];
                vh_[2*p+1][0] = t4[2]; vh_[2*p+1][1] = t4[3];
                ldsm4t(t4, vB + 8192u + off);
                vl_[2*p][0] = t4[0]; vl_[2*p][1] = t4[1];
                vl_[2*p+1][0] = t4[2]; vl_[2*p+1][1] = t4[3];
            }
            #pragma unroll
            for (int mi = 0; mi < 2; mi++)
                #pragma unroll
                for (int nj = 0; nj < 8; nj++) {
                    mma16816(o[mi][nj], ph_[mi], vl_[nj][0], vl_[nj][1]);
                    mma16816(o[mi][nj], pl_[mi], vh_[nj][0], vh_[nj][1]);
                    mma16816(o[mi][nj], ph_[mi], vh_[nj][0], vh_[nj][1]);
                }
        }
        __syncthreads();
    }

    // ---- normalize + write split bf16 output ----
    #pragma unroll
    for (int i = 0; i < 4; i++) {
        ls[i] += __shfl_xor_sync(0xffffffffu, ls[i], 1);
        ls[i] += __shfl_xor_sync(0xffffffffu, ls[i], 2);
        ls[i] = 1.f / ls[i];
    }
    #pragma unroll
    for (int mi = 0; mi < 2; mi++) {
        int r0 = R0 + mi * 16 + g;
        #pragma unroll
        for (int nj = 0; nj < 8; nj++) {
            int c = h * DHEAD + nj * 8 + q4 * 2;
            float v00 = o[mi][nj][0] * ls[2*mi],     v01 = o[mi][nj][1] * ls[2*mi];
            float v10 = o[mi][nj][2] * ls[2*mi + 1], v11 = o[mi][nj][3] * ls[2*mi + 1];
            bf16 ha, la, hb, lb;
            size_t a0 = ((size_t)r0 * NPOS + n) * CCH + c;
            fsplit(v00, ha, la); fsplit(v01, hb, lb);
            *(uint32_t*)&g_aoh[a0] = pack2(ha, hb);
            *(uint32_t*)&g_aol[a0] = pack2(la, lb);
            size_t a1 = ((size_t)(r0 + 8) * NPOS + n) * CCH + c;
            fsplit(v10, ha, la); fsplit(v11, hb, lb);
            *(uint32_t*)&g_aoh[a1] = pack2(ha, hb);
            *(uint32_t*)&g_aol[a1] = pack2(la, lb);
        }
    }
}

// ---------------------------------------------------------------------------
extern "C" void kernel_launch(void* const* d_in, const int* in_sizes, int n_in,
                              void* d_out, int out_size) {
    const float* x         = (const float*)d_in[0];
    const float* in_proj_w = (const float*)d_in[1];
    const float* in_proj_b = (const float*)d_in[2];
    const float* out_w     = (const float*)d_in[3];
    const float* out_b     = (const float*)d_in[4];
    float* out = (float*)d_out;

    const int gemm_smem = 2 * 49152;   // 96KB -> 2 CTAs/SM
    cudaFuncSetAttribute(gemm_qkv_tc, cudaFuncAttributeMaxDynamicSharedMemorySize, gemm_smem);
    cudaFuncSetAttribute(gemm_out_tc, cudaFuncAttributeMaxDynamicSharedMemorySize, gemm_smem);
    cudaFuncSetAttribute(attn_tc,     cudaFuncAttributeMaxDynamicSharedMemorySize, 131072);

    split_weights_kernel<<<(C3 * CCH + 255) / 256, 256>>>(in_proj_w, out_w);
    {
        dim3 grid(CCH / 32, BATCH * HH * 2);
        dim3 blk(32, 8);
        rearrange_kernel<<<grid, blk>>>(x);
    }
    {
        dim3 grid(C3 / 128, MTOT / 64);
        gemm_qkv_tc<<<grid, 256, gemm_smem>>>(in_proj_b);
    }
    attn_tc<<<NPOS * HEADS, 256, 131072>>>();
    {
        dim3 grid(CCH / 128, MTOT / 64);
        gemm_out_tc<<<grid, 256, gemm_smem>>>(out_b, out);
    }
}

// round 13
// speedup vs baseline: 1.1879x; 1.0474x over previous
#include <cuda_runtime.h>
#include <cuda_bf16.h>
#include <math.h>
#include <stdint.h>

#define BATCH 16
#define CCH   512
#define HH    64
#define WW    64
#define LWIN  256
#define NPOS  256
#define MTOT  65536
#define C3    1536
#define HEADS 8
#define DHEAD 64

typedef __nv_bfloat16 bf16;

// Pre-split bf16 hi/lo scratch
__device__ bf16 g_xh[(size_t)MTOT * CCH];
__device__ bf16 g_xl[(size_t)MTOT * CCH];
__device__ bf16 g_qh[(size_t)MTOT * C3];
__device__ bf16 g_ql[(size_t)MTOT * C3];
__device__ bf16 g_aoh[(size_t)MTOT * CCH];
__device__ bf16 g_aol[(size_t)MTOT * CCH];
__device__ bf16 g_wh[(size_t)C3 * CCH];
__device__ bf16 g_wl[(size_t)C3 * CCH];
__device__ bf16 g_owh[(size_t)CCH * CCH];
__device__ bf16 g_owl[(size_t)CCH * CCH];

// ---------------------------------------------------------------------------
// helpers
// ---------------------------------------------------------------------------
__device__ __forceinline__ void fsplit(float v, bf16& h, bf16& l) {
    h = __float2bfloat16_rn(v);
    l = __float2bfloat16_rn(v - __bfloat162float(h));
}
__device__ __forceinline__ uint32_t pack2(bf16 a, bf16 b) {
    return ((uint32_t)__bfloat16_as_ushort(b) << 16) | (uint32_t)__bfloat16_as_ushort(a);
}
__device__ __forceinline__ uint32_t cvta_s(const void* p) {
    return (uint32_t)__cvta_generic_to_shared(p);
}
__device__ __forceinline__ void cpa16(uint32_t d, const void* s) {
    asm volatile("cp.async.cg.shared.global [%0], [%1], 16;" :: "r"(d), "l"(s));
}
__device__ __forceinline__ void cp_commit() { asm volatile("cp.async.commit_group;"); }
__device__ __forceinline__ void cp_wait0()  { asm volatile("cp.async.wait_group 0;"); }
__device__ __forceinline__ void cp_wait1()  { asm volatile("cp.async.wait_group 1;"); }

__device__ __forceinline__ void ldsm4(uint32_t r[4], uint32_t a) {
    asm volatile("ldmatrix.sync.aligned.m8n8.x4.shared.b16 {%0,%1,%2,%3}, [%4];"
                 : "=r"(r[0]), "=r"(r[1]), "=r"(r[2]), "=r"(r[3]) : "r"(a));
}
__device__ __forceinline__ void ldsm4t(uint32_t r[4], uint32_t a) {
    asm volatile("ldmatrix.sync.aligned.m8n8.x4.trans.shared.b16 {%0,%1,%2,%3}, [%4];"
                 : "=r"(r[0]), "=r"(r[1]), "=r"(r[2]), "=r"(r[3]) : "r"(a));
}
__device__ __forceinline__ void mma16816(float c[4], const uint32_t a[4],
                                         uint32_t b0, uint32_t b1) {
    asm volatile(
        "mma.sync.aligned.m16n8k16.row.col.f32.bf16.bf16.f32 "
        "{%0,%1,%2,%3}, {%4,%5,%6,%7}, {%8,%9}, {%0,%1,%2,%3};"
        : "+f"(c[0]), "+f"(c[1]), "+f"(c[2]), "+f"(c[3])
        : "r"(a[0]), "r"(a[1]), "r"(a[2]), "r"(a[3]), "r"(b0), "r"(b1));
}

// ---------------------------------------------------------------------------
// Kernel: split weights into bf16 hi/lo
// ---------------------------------------------------------------------------
__global__ void split_weights_kernel(const float* __restrict__ w,
                                     const float* __restrict__ ow) {
    int i = blockIdx.x * blockDim.x + threadIdx.x;
    if (i < C3 * CCH)  fsplit(w[i],  g_wh[i],  g_wl[i]);
    if (i < CCH * CCH) fsplit(ow[i], g_owh[i], g_owl[i]);
}

// ---------------------------------------------------------------------------
// Kernel: layout transform x(B,C,H,W) -> split bf16 (m, c)
// ---------------------------------------------------------------------------
__global__ void rearrange_kernel(const float* __restrict__ x) {
    __shared__ float tile[32][33];
    int c0   = blockIdx.x * 32;
    int t    = blockIdx.y;
    int colt = t & 1;
    int row  = (t >> 1) & 63;
    int b    = t >> 7;
    int tx = threadIdx.x;
    int ty = threadIdx.y;

    #pragma unroll
    for (int r = 0; r < 4; r++) {
        int c   = c0 + ty + r * 8;
        int col = colt * 32 + tx;
        tile[ty + r * 8][tx] =
            x[(((size_t)b * CCH + c) * HH + row) * WW + col];
    }
    __syncthreads();

    int nh = row >> 4;
    int ii = row & 15;
    #pragma unroll
    for (int r = 0; r < 4; r++) {
        int col = colt * 32 + ty + r * 8;
        int nw  = col >> 4;
        int jj  = col & 15;
        int l   = b * 16 + nh * 4 + nw;
        int n_  = ii * 16 + jj;
        size_t m = (size_t)l * NPOS + n_;
        float v = tile[tx][ty + r * 8];
        bf16 hh, ll; fsplit(v, hh, ll);
        g_xh[m * CCH + c0 + tx] = hh;
        g_xl[m * CCH + c0 + tx] = ll;
    }
}

// ---------------------------------------------------------------------------
// GEMM mainloop (R11 proven), BM=64 x BN=128, 96KB -> 2 CTAs/SM.
// ---------------------------------------------------------------------------
__device__ __forceinline__ void gemm_mainloop(
    const bf16* __restrict__ Ah, const bf16* __restrict__ Al,
    const bf16* __restrict__ Bh, const bf16* __restrict__ Bl,
    int m0, int n0, bf16* dsm, float acc[2][4][4]) {

    const int tid  = threadIdx.x;
    const int lane = tid & 31;
    const int wid  = tid >> 5;
    const int wm   = wid & 1;
    const int wn   = wid >> 1;

    const int ar  = tid >> 2;
    const int ac0 = (tid & 3) * 2;
    const int br  = tid >> 1;
    const int bc0 = (tid & 1) * 4;

    const bf16* gAh = Ah + (size_t)(m0 + ar) * CCH;
    const bf16* gAl = Al + (size_t)(m0 + ar) * CCH;
    const bf16* gBh = Bh + (size_t)(n0 + br) * CCH;
    const bf16* gBl = Bl + (size_t)(n0 + br) * CCH;

    uint32_t sbase = cvta_s(dsm);
    const uint32_t arow = (uint32_t)(ar << 7);
    const uint32_t brow = (uint32_t)(br << 7);

    auto stage = [&](int it) {
        int kb = it * 64;
        uint32_t b = sbase + (uint32_t)(it & 1) * 49152u;
        #pragma unroll
        for (int j = 0; j < 2; j++) {
            int c = ac0 + j;
            uint32_t so = arow + (uint32_t)((c ^ (ar & 7)) << 4);
            cpa16(b + so,          gAh + kb + c * 8);
            cpa16(b + 8192u + so,  gAl + kb + c * 8);
        }
        #pragma unroll
        for (int j = 0; j < 4; j++) {
            int c = bc0 + j;
            uint32_t so = brow + (uint32_t)((c ^ (br & 7)) << 4);
            cpa16(b + 16384u + so, gBh + kb + c * 8);
            cpa16(b + 32768u + so, gBl + kb + c * 8);
        }
    };

    auto compute = [&](int it) {
        uint32_t b  = sbase + (uint32_t)(it & 1) * 49152u;
        uint32_t aB = b;
        uint32_t bB = b + 16384u;
        #pragma unroll
        for (int ks = 0; ks < 4; ks++) {
            uint32_t aH[2][4], aL[2][4];
            #pragma unroll
            for (int mi = 0; mi < 2; mi++) {
                int row = wm * 32 + mi * 16 + (lane & 15);
                int cc  = 2 * ks + (lane >> 4);
                uint32_t off = (uint32_t)(row << 7) + (uint32_t)(((cc ^ (row & 7))) << 4);
                ldsm4(aH[mi], aB + off);
                ldsm4(aL[mi], aB + 8192u + off);
            }
            uint32_t bH[4][2], bL[4][2];
            #pragma unroll
            for (int p = 0; p < 2; p++) {
                int row = wn * 32 + p * 16 + ((lane >> 4) << 3) + (lane & 7);
                int cc  = 2 * ks + ((lane >> 3) & 1);
                uint32_t off = (uint32_t)(row << 7) + (uint32_t)(((cc ^ (row & 7))) << 4);
                uint32_t t4[4];
                ldsm4(t4, bB + off);
                bH[2*p][0] = t4[0]; bH[2*p][1] = t4[1];
                bH[2*p+1][0] = t4[2]; bH[2*p+1][1] = t4[3];
                ldsm4(t4, bB + 16384u + off);
                bL[2*p][0] = t4[0]; bL[2*p][1] = t4[1];
                bL[2*p+1][0] = t4[2]; bL[2*p+1][1] = t4[3];
            }
            #pragma unroll
            for (int mi = 0; mi < 2; mi++)
                #pragma unroll
                for (int nj = 0; nj < 4; nj++) {
                    mma16816(acc[mi][nj], aH[mi], bL[nj][0], bL[nj][1]);
                    mma16816(acc[mi][nj], aL[mi], bH[nj][0], bH[nj][1]);
                    mma16816(acc[mi][nj], aH[mi], bH[nj][0], bH[nj][1]);
                }
        }
    };

    stage(0); cp_commit();
    for (int it = 0; it < 8; it++) {
        cp_wait0();
        __syncthreads();
        if (it < 7) { stage(it + 1); cp_commit(); }
        compute(it);
    }
}

// QKV projection: writes split bf16 qkv (with bias, q pre-scaled by 1/8)
__global__ __launch_bounds__(256, 2) void gemm_qkv_tc(const float* __restrict__ bias) {
    extern __shared__ bf16 dsm[];
    int m0 = blockIdx.y * 64;
    int n0 = blockIdx.x * 128;
    float acc[2][4][4] = {};
    gemm_mainloop(g_xh, g_xl, g_wh, g_wl, m0, n0, dsm, acc);

    const int lane = threadIdx.x & 31, wid = threadIdx.x >> 5;
    const int wm = wid & 1, wn = wid >> 1;
    const int g = lane >> 2, q4 = lane & 3;
    #pragma unroll
    for (int mi = 0; mi < 2; mi++) {
        int r = m0 + wm * 32 + mi * 16 + g;
        #pragma unroll
        for (int nj = 0; nj < 4; nj++) {
            int c = n0 + wn * 32 + nj * 8 + q4 * 2;
            float sc = (c < CCH) ? 0.125f : 1.0f;
            float b0 = bias[c], b1 = bias[c + 1];
            float v00 = (acc[mi][nj][0] + b0) * sc;
            float v01 = (acc[mi][nj][1] + b1) * sc;
            float v10 = (acc[mi][nj][2] + b0) * sc;
            float v11 = (acc[mi][nj][3] + b1) * sc;
            bf16 ha, la, hb, lb;
            fsplit(v00, ha, la); fsplit(v01, hb, lb);
            *(uint32_t*)&g_qh[(size_t)r * C3 + c] = pack2(ha, hb);
            *(uint32_t*)&g_ql[(size_t)r * C3 + c] = pack2(la, lb);
            fsplit(v10, ha, la); fsplit(v11, hb, lb);
            *(uint32_t*)&g_qh[(size_t)(r + 8) * C3 + c] = pack2(ha, hb);
            *(uint32_t*)&g_ql[(size_t)(r + 8) * C3 + c] = pack2(la, lb);
        }
    }
}

__device__ __forceinline__ size_t spatial_index(int m, int c) {
    int l = m >> 8, n_ = m & 255;
    int b = l >> 4, rem = l & 15;
    int nh = rem >> 2, nw = rem & 3;
    int ii = n_ >> 4, jj = n_ & 15;
    int srow = nh * 16 + ii, scol = nw * 16 + jj;
    return (((size_t)b * CCH + c) * HH + srow) * WW + scol;
}

// Output projection + scatter to (B, C, H, W)
__global__ __launch_bounds__(256, 2) void gemm_out_tc(const float* __restrict__ bias,
                                                      float* __restrict__ Out) {
    extern __shared__ bf16 dsm[];
    int m0 = blockIdx.y * 64;
    int n0 = blockIdx.x * 128;
    float acc[2][4][4] = {};
    gemm_mainloop(g_aoh, g_aol, g_owh, g_owl, m0, n0, dsm, acc);

    const int lane = threadIdx.x & 31, wid = threadIdx.x >> 5;
    const int wm = wid & 1, wn = wid >> 1;
    const int g = lane >> 2, q4 = lane & 3;
    #pragma unroll
    for (int mi = 0; mi < 2; mi++) {
        int r = m0 + wm * 32 + mi * 16 + g;
        #pragma unroll
        for (int nj = 0; nj < 4; nj++) {
            int c = n0 + wn * 32 + nj * 8 + q4 * 2;
            float b0 = bias[c], b1 = bias[c + 1];
            Out[spatial_index(r, c)]         = acc[mi][nj][0] + b0;
            Out[spatial_index(r, c + 1)]     = acc[mi][nj][1] + b1;
            Out[spatial_index(r + 8, c)]     = acc[mi][nj][2] + b0;
            Out[spatial_index(r + 8, c + 1)] = acc[mi][nj][3] + b1;
        }
    }
}

// ---------------------------------------------------------------------------
// Tensor-core flash attention, QUERY-SPLIT for 2 CTAs/SM.
// Grid 4096: bx -> n = bx&255, h = (bx>>8)&7, qhalf = bx>>11.
// CTA handles 128 query rows (qhalf*128 ..). Warp w owns 16 rows.
// smem 96KB: Qh@0 (16KB), Ql@16384, kv buf b at 32768+b*32768:
//   Kh +0, Kl +8192, Vh +16384, Vl +24576 (64 keys per chunk).
// ---------------------------------------------------------------------------
__global__ __launch_bounds__(256, 2) void attn_tc() {
    extern __shared__ bf16 dsm[];
    const int bx  = blockIdx.x;
    const int n   = bx & 255;
    const int h   = (bx >> 8) & 7;
    const int qhf = bx >> 11;          // 0 or 1
    const int tid = threadIdx.x;
    const int lane = tid & 31;
    const int wid  = tid >> 5;
    const int R0   = wid * 16;         // local query row base (0..112)
    const int g = lane >> 2, q4 = lane & 3;

    uint32_t sbase = cvta_s(dsm);
    const uint32_t kvbase = sbase + 32768u;

    // ---- load Q: 128 rows, 2 threads per row ----
    {
        int row = tid >> 1;                      // 0..127
        int c0  = (tid & 1) * 4;                 // chunk base
        size_t ro = ((size_t)(qhf * 128 + row) * NPOS + n) * C3 + h * DHEAD;
        uint32_t rowo = (uint32_t)(row << 7);
        #pragma unroll
        for (int j = 0; j < 4; j++) {
            int c = c0 + j;
            uint32_t so = rowo + (uint32_t)((c ^ (row & 7)) << 4);
            cpa16(sbase + so,           g_qh + ro + c * 8);
            cpa16(sbase + 16384u + so,  g_ql + ro + c * 8);
        }
    }
    cp_commit();

    auto load_kv = [&](int ch, int b) {
        int k0 = ch * 64;
        uint32_t kvb = kvbase + (uint32_t)b * 32768u;
        #pragma unroll
        for (int j = 0; j < 2; j++) {
            int id = tid * 2 + j;
            int r = id >> 3, c = id & 7;
            size_t gro = ((size_t)(k0 + r) * NPOS + n) * C3 + h * DHEAD + c * 8;
            uint32_t dst = (uint32_t)(r << 7) + (uint32_t)((c ^ (r & 7)) << 4);
            cpa16(kvb + dst,          g_qh + gro + 512);   // Kh
            cpa16(kvb + 8192u + dst,  g_ql + gro + 512);   // Kl
            cpa16(kvb + 16384u + dst, g_qh + gro + 1024);  // Vh
            cpa16(kvb + 24576u + dst, g_ql + gro + 1024);  // Vl
        }
    };

    load_kv(0, 0); cp_commit();

    float o[8][4];
    #pragma unroll
    for (int nj = 0; nj < 8; nj++)
        #pragma unroll
        for (int i = 0; i < 4; i++) o[nj][i] = 0.f;
    float ls[2] = {0.f, 0.f};

    for (int ch = 0; ch < 4; ch++) {
        if (ch < 3) { load_kv(ch + 1, (ch + 1) & 1); cp_commit(); cp_wait1(); }
        else        { cp_wait0(); }
        __syncthreads();

        uint32_t kB = kvbase + (uint32_t)(ch & 1) * 32768u;
        uint32_t vB = kB + 16384u;

        // ---- S = Q K^T (16 q-rows x 64 keys per warp) ----
        float s[8][4];
        #pragma unroll
        for (int nj = 0; nj < 8; nj++)
            #pragma unroll
            for (int i = 0; i < 4; i++) s[nj][i] = 0.f;

        #pragma unroll
        for (int ks = 0; ks < 4; ks++) {
            uint32_t qh_[4], ql_[4];
            {
                int row = R0 + (lane & 15);
                int cc  = 2 * ks + (lane >> 4);
                uint32_t off = (uint32_t)(row << 7) + (uint32_t)((cc ^ (row & 7)) << 4);
                ldsm4(qh_, sbase + off);
                ldsm4(ql_, sbase + 16384u + off);
            }
            uint32_t kh_[8][2], kl_[8][2];
            #pragma unroll
            for (int p = 0; p < 4; p++) {
                int row = p * 16 + ((lane >> 4) << 3) + (lane & 7);
                int cc  = 2 * ks + ((lane >> 3) & 1);
                uint32_t off = (uint32_t)(row << 7) + (uint32_t)((cc ^ (row & 7)) << 4);
                uint32_t t4[4];
                ldsm4(t4, kB + off);
                kh_[2*p][0] = t4[0]; kh_[2*p][1] = t4[1];
                kh_[2*p+1][0] = t4[2]; kh_[2*p+1][1] = t4[3];
                ldsm4(t4, kB + 8192u + off);
                kl_[2*p][0] = t4[0]; kl_[2*p][1] = t4[1];
                kl_[2*p+1][0] = t4[2]; kl_[2*p+1][1] = t4[3];
            }
            #pragma unroll
            for (int nj = 0; nj < 8; nj++) {
                mma16816(s[nj], qh_, kl_[nj][0], kl_[nj][1]);
                mma16816(s[nj], ql_, kh_[nj][0], kh_[nj][1]);
                mma16816(s[nj], qh_, kh_[nj][0], kh_[nj][1]);
            }
        }

        // ---- exp + row sums ----
        #pragma unroll
        for (int nj = 0; nj < 8; nj++)
            #pragma unroll
            for (int i = 0; i < 4; i++) {
                float p = __expf(fminf(s[nj][i], 25.f));
                s[nj][i] = p;
                ls[i >> 1] += p;
            }

        // ---- O += P V ----
        #pragma unroll
        for (int ks = 0; ks < 4; ks++) {
            uint32_t ph_[4], pl_[4];
            #pragma unroll
            for (int half = 0; half < 2; half++) {
                int t = 2 * ks + half;
                bf16 h0, l0, h1, l1;
                // A-frag order: fill order IS the frag order (R3 lesson).
                fsplit(s[t][0], h0, l0); fsplit(s[t][1], h1, l1);
                ph_[half * 2 + 0] = pack2(h0, h1);
                pl_[half * 2 + 0] = pack2(l0, l1);
                fsplit(s[t][2], h0, l0); fsplit(s[t][3], h1, l1);
                ph_[half * 2 + 1] = pack2(h0, h1);
                pl_[half * 2 + 1] = pack2(l0, l1);
            }
            uint32_t vh_[8][2], vl_[8][2];
            #pragma unroll
            for (int p = 0; p < 4; p++) {
                int row = 16 * ks + ((lane >> 3) & 1) * 8 + (lane & 7);
                int cc  = 2 * p + (lane >> 4);
                uint32_t off = (uint32_t)(row << 7) + (uint32_t)((cc ^ (row & 7)) << 4);
                uint32_t t4[4];
                ldsm4t(t4, vB + off);
                vh_[2*p][0] = t4[0]; vh_[2*p][1] = t4[1];
                vh_[2*p+1][0] = t4[2]; vh_[2*p+1][1] = t4[3];
                ldsm4t(t4, vB + 8192u + off);
                vl_[2*p][0] = t4[0]; vl_[2*p][1] = t4[1];
                vl_[2*p+1][0] = t4[2]; vl_[2*p+1][1] = t4[3];
            }
            #pragma unroll
            for (int nj = 0; nj < 8; nj++) {
                mma16816(o[nj], ph_, vl_[nj][0], vl_[nj][1]);
                mma16816(o[nj], pl_, vh_[nj][0], vh_[nj][1]);
                mma16816(o[nj], ph_, vh_[nj][0], vh_[nj][1]);
            }
        }
        __syncthreads();
    }

    // ---- normalize + write split bf16 output ----
    #pragma unroll
    for (int i = 0; i < 2; i++) {
        ls[i] += __shfl_xor_sync(0xffffffffu, ls[i], 1);
        ls[i] += __shfl_xor_sync(0xffffffffu, ls[i], 2);
        ls[i] = 1.f / ls[i];
    }
    {
        int r0 = qhf * 128 + R0 + g;
        #pragma unroll
        for (int nj = 0; nj < 8; nj++) {
            int c = h * DHEAD + nj * 8 + q4 * 2;
            float v00 = o[nj][0] * ls[0], v01 = o[nj][1] * ls[0];
            float v10 = o[nj][2] * ls[1], v11 = o[nj][3] * ls[1];
            bf16 ha, la, hb, lb;
            size_t a0 = ((size_t)r0 * NPOS + n) * CCH + c;
            fsplit(v00, ha, la); fsplit(v01, hb, lb);
            *(uint32_t*)&g_aoh[a0] = pack2(ha, hb);
            *(uint32_t*)&g_aol[a0] = pack2(la, lb);
            size_t a1 = ((size_t)(r0 + 8) * NPOS + n) * CCH + c;
            fsplit(v10, ha, la); fsplit(v11, hb, lb);
            *(uint32_t*)&g_aoh[a1] = pack2(ha, hb);
            *(uint32_t*)&g_aol[a1] = pack2(la, lb);
        }
    }
}

// ---------------------------------------------------------------------------
extern "C" void kernel_launch(void* const* d_in, const int* in_sizes, int n_in,
                              void* d_out, int out_size) {
    const float* x         = (const float*)d_in[0];
    const float* in_proj_w = (const float*)d_in[1];
    const float* in_proj_b = (const float*)d_in[2];
    const float* out_w     = (const float*)d_in[3];
    const float* out_b     = (const float*)d_in[4];
    float* out = (float*)d_out;

    const int gemm_smem = 2 * 49152;   // 96KB -> 2 CTAs/SM
    const int attn_smem = 32768 + 2 * 32768;   // 96KB -> 2 CTAs/SM
    cudaFuncSetAttribute(gemm_qkv_tc, cudaFuncAttributeMaxDynamicSharedMemorySize, gemm_smem);
    cudaFuncSetAttribute(gemm_out_tc, cudaFuncAttributeMaxDynamicSharedMemorySize, gemm_smem);
    cudaFuncSetAttribute(attn_tc,     cudaFuncAttributeMaxDynamicSharedMemorySize, attn_smem);

    split_weights_kernel<<<(C3 * CCH + 255) / 256, 256>>>(in_proj_w, out_w);
    {
        dim3 grid(CCH / 32, BATCH * HH * 2);
        dim3 blk(32, 8);
        rearrange_kernel<<<grid, blk>>>(x);
    }
    {
        dim3 grid(C3 / 128, MTOT / 64);
        gemm_qkv_tc<<<grid, 256, gemm_smem>>>(in_proj_b);
    }
    attn_tc<<<NPOS * HEADS * 2, 256, attn_smem>>>();
    {
        dim3 grid(CCH / 128, MTOT / 64);
        gemm_out_tc<<<grid, 256, gemm_smem>>>(out_b, out);
    }
}

// round 17
// speedup vs baseline: 1.3489x; 1.1355x over previous
#include <cuda_runtime.h>
#include <cuda_bf16.h>
#include <cuda_fp16.h>
#include <math.h>
#include <stdint.h>

#define BATCH 16
#define CCH   512
#define HH    64
#define WW    64
#define LWIN  256
#define NPOS  256
#define MTOT  65536
#define C3    1536
#define HEADS 8
#define DHEAD 64

typedef __nv_bfloat16 bf16;
typedef __half fp16;

// qkv GEMM inputs: split bf16 (3-product, high accuracy)
__device__ bf16 g_xh[(size_t)MTOT * CCH];
__device__ bf16 g_xl[(size_t)MTOT * CCH];
__device__ bf16 g_wh[(size_t)C3 * CCH];
__device__ bf16 g_wl[(size_t)C3 * CCH];
// qkv output (fp16): q = double-split (g_qh+g_ql), k/v = single (g_qh only)
__device__ fp16 g_qh[(size_t)MTOT * C3];
__device__ fp16 g_ql[(size_t)MTOT * C3];
// attention out: double-split fp16
__device__ fp16 g_aoh[(size_t)MTOT * CCH];
__device__ fp16 g_aol[(size_t)MTOT * CCH];
// out-proj weights: single fp16
__device__ fp16 g_owh[(size_t)CCH * CCH];

// ---------------------------------------------------------------------------
// helpers
// ---------------------------------------------------------------------------
__device__ __forceinline__ void fsplit(float v, bf16& h, bf16& l) {
    h = __float2bfloat16_rn(v);
    l = __float2bfloat16_rn(v - __bfloat162float(h));
}
__device__ __forceinline__ void hsplit(float v, fp16& h, fp16& l) {
    h = __float2half_rn(v);
    l = __float2half_rn(v - __half2float(h));
}
__device__ __forceinline__ uint32_t pack2h(fp16 a, fp16 b) {
    return ((uint32_t)__half_as_ushort(b) << 16) | (uint32_t)__half_as_ushort(a);
}
__device__ __forceinline__ uint32_t cvta_s(const void* p) {
    return (uint32_t)__cvta_generic_to_shared(p);
}
__device__ __forceinline__ void cpa16(uint32_t d, const void* s) {
    asm volatile("cp.async.cg.shared.global [%0], [%1], 16;" :: "r"(d), "l"(s));
}
__device__ __forceinline__ void cp_commit() { asm volatile("cp.async.commit_group;"); }
__device__ __forceinline__ void cp_wait0()  { asm volatile("cp.async.wait_group 0;"); }
__device__ __forceinline__ void cp_wait1()  { asm volatile("cp.async.wait_group 1;"); }

__device__ __forceinline__ void ldsm4(uint32_t r[4], uint32_t a) {
    asm volatile("ldmatrix.sync.aligned.m8n8.x4.shared.b16 {%0,%1,%2,%3}, [%4];"
                 : "=r"(r[0]), "=r"(r[1]), "=r"(r[2]), "=r"(r[3]) : "r"(a));
}
__device__ __forceinline__ void ldsm4t(uint32_t r[4], uint32_t a) {
    asm volatile("ldmatrix.sync.aligned.m8n8.x4.trans.shared.b16 {%0,%1,%2,%3}, [%4];"
                 : "=r"(r[0]), "=r"(r[1]), "=r"(r[2]), "=r"(r[3]) : "r"(a));
}
__device__ __forceinline__ void mma16816(float c[4], const uint32_t a[4],
                                         uint32_t b0, uint32_t b1) {
    asm volatile(
        "mma.sync.aligned.m16n8k16.row.col.f32.bf16.bf16.f32 "
        "{%0,%1,%2,%3}, {%4,%5,%6,%7}, {%8,%9}, {%0,%1,%2,%3};"
        : "+f"(c[0]), "+f"(c[1]), "+f"(c[2]), "+f"(c[3])
        : "r"(a[0]), "r"(a[1]), "r"(a[2]), "r"(a[3]), "r"(b0), "r"(b1));
}
__device__ __forceinline__ void mma16816h(float c[4], const uint32_t a[4],
                                          uint32_t b0, uint32_t b1) {
    asm volatile(
        "mma.sync.aligned.m16n8k16.row.col.f32.f16.f16.f32 "
        "{%0,%1,%2,%3}, {%4,%5,%6,%7}, {%8,%9}, {%0,%1,%2,%3};"
        : "+f"(c[0]), "+f"(c[1]), "+f"(c[2]), "+f"(c[3])
        : "r"(a[0]), "r"(a[1]), "r"(a[2]), "r"(a[3]), "r"(b0), "r"(b1));
}

// ---------------------------------------------------------------------------
// Kernel: split/convert weights
// ---------------------------------------------------------------------------
__global__ void split_weights_kernel(const float* __restrict__ w,
                                     const float* __restrict__ ow) {
    int i = blockIdx.x * blockDim.x + threadIdx.x;
    if (i < C3 * CCH)  fsplit(w[i],  g_wh[i],  g_wl[i]);
    if (i < CCH * CCH) g_owh[i] = __float2half_rn(ow[i]);
}

// ---------------------------------------------------------------------------
// Kernel: layout transform x(B,C,H,W) -> split bf16 (m, c)
// ---------------------------------------------------------------------------
__global__ void rearrange_kernel(const float* __restrict__ x) {
    __shared__ float tile[32][33];
    int c0   = blockIdx.x * 32;
    int t    = blockIdx.y;
    int colt = t & 1;
    int row  = (t >> 1) & 63;
    int b    = t >> 7;
    int tx = threadIdx.x;
    int ty = threadIdx.y;

    #pragma unroll
    for (int r = 0; r < 4; r++) {
        int c   = c0 + ty + r * 8;
        int col = colt * 32 + tx;
        tile[ty + r * 8][tx] =
            x[(((size_t)b * CCH + c) * HH + row) * WW + col];
    }
    __syncthreads();

    int nh = row >> 4;
    int ii = row & 15;
    #pragma unroll
    for (int r = 0; r < 4; r++) {
        int col = colt * 32 + ty + r * 8;
        int nw  = col >> 4;
        int jj  = col & 15;
        int l   = b * 16 + nh * 4 + nw;
        int n_  = ii * 16 + jj;
        size_t m = (size_t)l * NPOS + n_;
        float v = tile[tx][ty + r * 8];
        bf16 hh, ll; fsplit(v, hh, ll);
        g_xh[m * CCH + c0 + tx] = hh;
        g_xl[m * CCH + c0 + tx] = ll;
    }
}

// ---------------------------------------------------------------------------
// bf16 3-product GEMM mainloop (R13 proven), BM=64 x BN=128, 96KB, 2 CTAs/SM.
// ---------------------------------------------------------------------------
__device__ __forceinline__ void gemm_mainloop(
    const bf16* __restrict__ Ah, const bf16* __restrict__ Al,
    const bf16* __restrict__ Bh, const bf16* __restrict__ Bl,
    int m0, int n0, char* dsm, float acc[2][4][4]) {

    const int tid  = threadIdx.x;
    const int lane = tid & 31;
    const int wid  = tid >> 5;
    const int wm   = wid & 1;
    const int wn   = wid >> 1;

    const int ar  = tid >> 2;
    const int ac0 = (tid & 3) * 2;
    const int br  = tid >> 1;
    const int bc0 = (tid & 1) * 4;

    const bf16* gAh = Ah + (size_t)(m0 + ar) * CCH;
    const bf16* gAl = Al + (size_t)(m0 + ar) * CCH;
    const bf16* gBh = Bh + (size_t)(n0 + br) * CCH;
    const bf16* gBl = Bl + (size_t)(n0 + br) * CCH;

    uint32_t sbase = cvta_s(dsm);
    const uint32_t arow = (uint32_t)(ar << 7);
    const uint32_t brow = (uint32_t)(br << 7);

    auto stage = [&](int it) {
        int kb = it * 64;
        uint32_t b = sbase + (uint32_t)(it & 1) * 49152u;
        #pragma unroll
        for (int j = 0; j < 2; j++) {
            int c = ac0 + j;
            uint32_t so = arow + (uint32_t)((c ^ (ar & 7)) << 4);
            cpa16(b + so,          gAh + kb + c * 8);
            cpa16(b + 8192u + so,  gAl + kb + c * 8);
        }
        #pragma unroll
        for (int j = 0; j < 4; j++) {
            int c = bc0 + j;
            uint32_t so = brow + (uint32_t)((c ^ (br & 7)) << 4);
            cpa16(b + 16384u + so, gBh + kb + c * 8);
            cpa16(b + 32768u + so, gBl + kb + c * 8);
        }
    };

    auto compute = [&](int it) {
        uint32_t b  = sbase + (uint32_t)(it & 1) * 49152u;
        uint32_t aB = b;
        uint32_t bB = b + 16384u;
        #pragma unroll
        for (int ks = 0; ks < 4; ks++) {
            uint32_t aH[2][4], aL[2][4];
            #pragma unroll
            for (int mi = 0; mi < 2; mi++) {
                int row = wm * 32 + mi * 16 + (lane & 15);
                int cc  = 2 * ks + (lane >> 4);
                uint32_t off = (uint32_t)(row << 7) + (uint32_t)(((cc ^ (row & 7))) << 4);
                ldsm4(aH[mi], aB + off);
                ldsm4(aL[mi], aB + 8192u + off);
            }
            uint32_t bH[4][2], bL[4][2];
            #pragma unroll
            for (int p = 0; p < 2; p++) {
                int row = wn * 32 + p * 16 + ((lane >> 4) << 3) + (lane & 7);
                int cc  = 2 * ks + ((lane >> 3) & 1);
                uint32_t off = (uint32_t)(row << 7) + (uint32_t)(((cc ^ (row & 7))) << 4);
                uint32_t t4[4];
                ldsm4(t4, bB + off);
                bH[2*p][0] = t4[0]; bH[2*p][1] = t4[1];
                bH[2*p+1][0] = t4[2]; bH[2*p+1][1] = t4[3];
                ldsm4(t4, bB + 16384u + off);
                bL[2*p][0] = t4[0]; bL[2*p][1] = t4[1];
                bL[2*p+1][0] = t4[2]; bL[2*p+1][1] = t4[3];
            }
            #pragma unroll
            for (int mi = 0; mi < 2; mi++)
                #pragma unroll
                for (int nj = 0; nj < 4; nj++) {
                    mma16816(acc[mi][nj], aH[mi], bL[nj][0], bL[nj][1]);
                    mma16816(acc[mi][nj], aL[mi], bH[nj][0], bH[nj][1]);
                    mma16816(acc[mi][nj], aH[mi], bH[nj][0], bH[nj][1]);
                }
        }
    };

    stage(0); cp_commit();
    for (int it = 0; it < 8; it++) {
        cp_wait0();
        __syncthreads();
        if (it < 7) { stage(it + 1); cp_commit(); }
        compute(it);
    }
}

// QKV projection: q (c<512) -> double-split fp16 (scaled 1/8); k/v -> single fp16
__global__ __launch_bounds__(256, 2) void gemm_qkv_tc(const float* __restrict__ bias) {
    extern __shared__ char dsmc[];
    int m0 = blockIdx.y * 64;
    int n0 = blockIdx.x * 128;
    float acc[2][4][4] = {};
    gemm_mainloop(g_xh, g_xl, g_wh, g_wl, m0, n0, dsmc, acc);

    const int lane = threadIdx.x & 31, wid = threadIdx.x >> 5;
    const int wm = wid & 1, wn = wid >> 1;
    const int g = lane >> 2, q4 = lane & 3;
    const bool is_q = (n0 < CCH);   // CTA c-range (128 wide) never straddles q/k/v
    #pragma unroll
    for (int mi = 0; mi < 2; mi++) {
        int r = m0 + wm * 32 + mi * 16 + g;
        #pragma unroll
        for (int nj = 0; nj < 4; nj++) {
            int c = n0 + wn * 32 + nj * 8 + q4 * 2;
            float b0 = bias[c], b1 = bias[c + 1];
            float v00 = acc[mi][nj][0] + b0;
            float v01 = acc[mi][nj][1] + b1;
            float v10 = acc[mi][nj][2] + b0;
            float v11 = acc[mi][nj][3] + b1;
            if (is_q) {
                v00 *= 0.125f; v01 *= 0.125f; v10 *= 0.125f; v11 *= 0.125f;
                fp16 ha, la, hb, lb;
                hsplit(v00, ha, la); hsplit(v01, hb, lb);
                *(uint32_t*)&g_qh[(size_t)r * C3 + c] = pack2h(ha, hb);
                *(uint32_t*)&g_ql[(size_t)r * C3 + c] = pack2h(la, lb);
                hsplit(v10, ha, la); hsplit(v11, hb, lb);
                *(uint32_t*)&g_qh[(size_t)(r + 8) * C3 + c] = pack2h(ha, hb);
                *(uint32_t*)&g_ql[(size_t)(r + 8) * C3 + c] = pack2h(la, lb);
            } else {
                *(uint32_t*)&g_qh[(size_t)r * C3 + c] =
                    pack2h(__float2half_rn(v00), __float2half_rn(v01));
                *(uint32_t*)&g_qh[(size_t)(r + 8) * C3 + c] =
                    pack2h(__float2half_rn(v10), __float2half_rn(v11));
            }
        }
    }
}

__device__ __forceinline__ size_t spatial_index(int m, int c) {
    int l = m >> 8, n_ = m & 255;
    int b = l >> 4, rem = l & 15;
    int nh = rem >> 2, nw = rem & 3;
    int ii = n_ >> 4, jj = n_ & 15;
    int srow = nh * 16 + ii, scol = nw * 16 + jj;
    return (((size_t)b * CCH + c) * HH + srow) * WW + scol;
}

// ---------------------------------------------------------------------------
// fp16 2-product GEMM mainloop for out-proj: A double-fp16, B single-fp16.
// BM=64 x BN=128. Stage 32KB (Ah 8K, Al 8K, B 16K), 2 stages = 64KB.
// ---------------------------------------------------------------------------
__device__ __forceinline__ void gemm_mainloop_h(
    const fp16* __restrict__ Ah, const fp16* __restrict__ Al,
    const fp16* __restrict__ Bw,
    int m0, int n0, char* dsm, float acc[2][4][4]) {

    const int tid  = threadIdx.x;
    const int lane = tid & 31;
    const int wid  = tid >> 5;
    const int wm   = wid & 1;
    const int wn   = wid >> 1;

    const int ar  = tid >> 2;
    const int ac0 = (tid & 3) * 2;
    const int br  = tid >> 1;
    const int bc0 = (tid & 1) * 4;

    const fp16* gAh = Ah + (size_t)(m0 + ar) * CCH;
    const fp16* gAl = Al + (size_t)(m0 + ar) * CCH;
    const fp16* gB  = Bw + (size_t)(n0 + br) * CCH;

    uint32_t sbase = cvta_s(dsm);
    const uint32_t arow = (uint32_t)(ar << 7);
    const uint32_t brow = (uint32_t)(br << 7);

    auto stage = [&](int it) {
        int kb = it * 64;
        uint32_t b = sbase + (uint32_t)(it & 1) * 32768u;
        #pragma unroll
        for (int j = 0; j < 2; j++) {
            int c = ac0 + j;
            uint32_t so = arow + (uint32_t)((c ^ (ar & 7)) << 4);
            cpa16(b + so,         gAh + kb + c * 8);
            cpa16(b + 8192u + so, gAl + kb + c * 8);
        }
        #pragma unroll
        for (int j = 0; j < 4; j++) {
            int c = bc0 + j;
            uint32_t so = brow + (uint32_t)((c ^ (br & 7)) << 4);
            cpa16(b + 16384u + so, gB + kb + c * 8);
        }
    };

    auto compute = [&](int it) {
        uint32_t b  = sbase + (uint32_t)(it & 1) * 32768u;
        uint32_t aB = b;
        uint32_t bB = b + 16384u;
        #pragma unroll
        for (int ks = 0; ks < 4; ks++) {
            uint32_t aH[2][4], aL[2][4];
            #pragma unroll
            for (int mi = 0; mi < 2; mi++) {
                int row = wm * 32 + mi * 16 + (lane & 15);
                int cc  = 2 * ks + (lane >> 4);
                uint32_t off = (uint32_t)(row << 7) + (uint32_t)(((cc ^ (row & 7))) << 4);
                ldsm4(aH[mi], aB + off);
                ldsm4(aL[mi], aB + 8192u + off);
            }
            uint32_t bH[4][2];
            #pragma unroll
            for (int p = 0; p < 2; p++) {
                int row = wn * 32 + p * 16 + ((lane >> 4) << 3) + (lane & 7);
                int cc  = 2 * ks + ((lane >> 3) & 1);
                uint32_t off = (uint32_t)(row << 7) + (uint32_t)(((cc ^ (row & 7))) << 4);
                uint32_t t4[4];
                ldsm4(t4, bB + off);
                bH[2*p][0] = t4[0]; bH[2*p][1] = t4[1];
                bH[2*p+1][0] = t4[2]; bH[2*p+1][1] = t4[3];
            }
            #pragma unroll
            for (int mi = 0; mi < 2; mi++)
                #pragma unroll
                for (int nj = 0; nj < 4; nj++) {
                    mma16816h(acc[mi][nj], aL[mi], bH[nj][0], bH[nj][1]);
                    mma16816h(acc[mi][nj], aH[mi], bH[nj][0], bH[nj][1]);
                }
        }
    };

    stage(0); cp_commit();
    for (int it = 0; it < 8; it++) {
        cp_wait0();
        __syncthreads();
        if (it < 7) { stage(it + 1); cp_commit(); }
        compute(it);
    }
}

// Output projection (fp16 2-product) + scatter to (B, C, H, W)
__global__ __launch_bounds__(256, 2) void gemm_out_tc(const float* __restrict__ bias,
                                                      float* __restrict__ Out) {
    extern __shared__ char dsmc[];
    int m0 = blockIdx.y * 64;
    int n0 = blockIdx.x * 128;
    float acc[2][4][4] = {};
    gemm_mainloop_h(g_aoh, g_aol, g_owh, m0, n0, dsmc, acc);

    const int lane = threadIdx.x & 31, wid = threadIdx.x >> 5;
    const int wm = wid & 1, wn = wid >> 1;
    const int g = lane >> 2, q4 = lane & 3;
    #pragma unroll
    for (int mi = 0; mi < 2; mi++) {
        int r = m0 + wm * 32 + mi * 16 + g;
        #pragma unroll
        for (int nj = 0; nj < 4; nj++) {
            int c = n0 + wn * 32 + nj * 8 + q4 * 2;
            float b0 = bias[c], b1 = bias[c + 1];
            Out[spatial_index(r, c)]         = acc[mi][nj][0] + b0;
            Out[spatial_index(r, c + 1)]     = acc[mi][nj][1] + b1;
            Out[spatial_index(r + 8, c)]     = acc[mi][nj][2] + b0;
            Out[spatial_index(r + 8, c + 1)] = acc[mi][nj][3] + b1;
        }
    }
}

// ---------------------------------------------------------------------------
// fp16 flash attention, query-split (2 CTAs per (n,h)), 2-product mma.
// Q double-fp16 (Qh/Ql), K single, V single, P double-fp16.
// smem 64KB: Qh@0 (16KB), Ql@16384, kv buf b at 32768+b*16384: K +0, V +8192.
// ---------------------------------------------------------------------------
__global__ __launch_bounds__(256, 2) void attn_tc() {
    extern __shared__ char dsmc[];
    const int bx  = blockIdx.x;
    const int n   = bx & 255;
    const int h   = (bx >> 8) & 7;
    const int qhf = bx >> 11;
    const int tid = threadIdx.x;
    const int lane = tid & 31;
    const int wid  = tid >> 5;
    const int R0   = wid * 16;
    const int g = lane >> 2, q4 = lane & 3;

    uint32_t sbase = cvta_s(dsmc);
    const uint32_t kvbase = sbase + 32768u;

    // ---- load Q: 128 rows, 2 threads per row (hi+lo) ----
    {
        int row = tid >> 1;
        int c0  = (tid & 1) * 4;
        size_t ro = ((size_t)(qhf * 128 + row) * NPOS + n) * C3 + h * DHEAD;
        uint32_t rowo = (uint32_t)(row << 7);
        #pragma unroll
        for (int j = 0; j < 4; j++) {
            int c = c0 + j;
            uint32_t so = rowo + (uint32_t)((c ^ (row & 7)) << 4);
            cpa16(sbase + so,          g_qh + ro + c * 8);
            cpa16(sbase + 16384u + so, g_ql + ro + c * 8);
        }
    }
    cp_commit();

    auto load_kv = [&](int ch, int b) {
        int k0 = ch * 64;
        uint32_t kvb = kvbase + (uint32_t)b * 16384u;
        #pragma unroll
        for (int j = 0; j < 2; j++) {
            int id = tid * 2 + j;
            int r = id >> 3, c = id & 7;
            size_t gro = ((size_t)(k0 + r) * NPOS + n) * C3 + h * DHEAD + c * 8;
            uint32_t dst = (uint32_t)(r << 7) + (uint32_t)((c ^ (r & 7)) << 4);
            cpa16(kvb + dst,         g_qh + gro + 512);   // K (single)
            cpa16(kvb + 8192u + dst, g_qh + gro + 1024);  // V (single)
        }
    };

    load_kv(0, 0); cp_commit();

    float o[8][4];
    #pragma unroll
    for (int nj = 0; nj < 8; nj++)
        #pragma unroll
        for (int i = 0; i < 4; i++) o[nj][i] = 0.f;
    float ls[2] = {0.f, 0.f};

    for (int ch = 0; ch < 4; ch++) {
        if (ch < 3) { load_kv(ch + 1, (ch + 1) & 1); cp_commit(); cp_wait1(); }
        else        { cp_wait0(); }
        __syncthreads();

        uint32_t kB = kvbase + (uint32_t)(ch & 1) * 16384u;
        uint32_t vB = kB + 8192u;

        // ---- S = Q K^T (2-product: Ql*K + Qh*K) ----
        float s[8][4];
        #pragma unroll
        for (int nj = 0; nj < 8; nj++)
            #pragma unroll
            for (int i = 0; i < 4; i++) s[nj][i] = 0.f;

        #pragma unroll
        for (int ks = 0; ks < 4; ks++) {
            uint32_t qh_[4], ql_[4];
            {
                int row = R0 + (lane & 15);
                int cc  = 2 * ks + (lane >> 4);
                uint32_t off = (uint32_t)(row << 7) + (uint32_t)((cc ^ (row & 7)) << 4);
                ldsm4(qh_, sbase + off);
                ldsm4(ql_, sbase + 16384u + off);
            }
            uint32_t kh_[8][2];
            #pragma unroll
            for (int p = 0; p < 4; p++) {
                int row = p * 16 + ((lane >> 4) << 3) + (lane & 7);
                int cc  = 2 * ks + ((lane >> 3) & 1);
                uint32_t off = (uint32_t)(row << 7) + (uint32_t)((cc ^ (row & 7)) << 4);
                uint32_t t4[4];
                ldsm4(t4, kB + off);
                kh_[2*p][0] = t4[0]; kh_[2*p][1] = t4[1];
                kh_[2*p+1][0] = t4[2]; kh_[2*p+1][1] = t4[3];
            }
            #pragma unroll
            for (int nj = 0; nj < 8; nj++) {
                mma16816h(s[nj], ql_, kh_[nj][0], kh_[nj][1]);
                mma16816h(s[nj], qh_, kh_[nj][0], kh_[nj][1]);
            }
        }

        // ---- exp + row sums ----
        #pragma unroll
        for (int nj = 0; nj < 8; nj++)
            #pragma unroll
            for (int i = 0; i < 4; i++) {
                float p = __expf(fminf(s[nj][i], 25.f));
                s[nj][i] = p;
                ls[i >> 1] += p;
            }

        // ---- O += P V (2-product: Pl*V + Ph*V) ----
        #pragma unroll
        for (int ks = 0; ks < 4; ks++) {
            uint32_t ph_[4], pl_[4];
            #pragma unroll
            for (int half = 0; half < 2; half++) {
                int t = 2 * ks + half;
                fp16 h0, l0, h1, l1;
                // A-frag order: fill order IS the frag order (R3 lesson).
                hsplit(s[t][0], h0, l0); hsplit(s[t][1], h1, l1);
                ph_[half * 2 + 0] = pack2h(h0, h1);
                pl_[half * 2 + 0] = pack2h(l0, l1);
                hsplit(s[t][2], h0, l0); hsplit(s[t][3], h1, l1);
                ph_[half * 2 + 1] = pack2h(h0, h1);
                pl_[half * 2 + 1] = pack2h(l0, l1);
            }
            uint32_t vh_[8][2];
            #pragma unroll
            for (int p = 0; p < 4; p++) {
                int row = 16 * ks + ((lane >> 3) & 1) * 8 + (lane & 7);
                int cc  = 2 * p + (lane >> 4);
                uint32_t off = (uint32_t)(row << 7) + (uint32_t)((cc ^ (row & 7)) << 4);
                uint32_t t4[4];
                ldsm4t(t4, vB + off);
                vh_[2*p][0] = t4[0]; vh_[2*p][1] = t4[1];
                vh_[2*p+1][0] = t4[2]; vh_[2*p+1][1] = t4[3];
            }
            #pragma unroll
            for (int nj = 0; nj < 8; nj++) {
                mma16816h(o[nj], pl_, vh_[nj][0], vh_[nj][1]);
                mma16816h(o[nj], ph_, vh_[nj][0], vh_[nj][1]);
            }
        }
        __syncthreads();
    }

    // ---- normalize + write double-split fp16 output ----
    #pragma unroll
    for (int i = 0; i < 2; i++) {
        ls[i] += __shfl_xor_sync(0xffffffffu, ls[i], 1);
        ls[i] += __shfl_xor_sync(0xffffffffu, ls[i], 2);
        ls[i] = 1.f / ls[i];
    }
    {
        int r0 = qhf * 128 + R0 + g;
        #pragma unroll
        for (int nj = 0; nj < 8; nj++) {
            int c = h * DHEAD + nj * 8 + q4 * 2;
            float v00 = o[nj][0] * ls[0], v01 = o[nj][1] * ls[0];
            float v10 = o[nj][2] * ls[1], v11 = o[nj][3] * ls[1];
            fp16 ha, la, hb, lb;
            size_t a0 = ((size_t)r0 * NPOS + n) * CCH + c;
            hsplit(v00, ha, la); hsplit(v01, hb, lb);
            *(uint32_t*)&g_aoh[a0] = pack2h(ha, hb);
            *(uint32_t*)&g_aol[a0] = pack2h(la, lb);
            size_t a1 = ((size_t)(r0 + 8) * NPOS + n) * CCH + c;
            hsplit(v10, ha, la); hsplit(v11, hb, lb);
            *(uint32_t*)&g_aoh[a1] = pack2h(ha, hb);
            *(uint32_t*)&g_aol[a1] = pack2h(la, lb);
        }
    }
}

// ---------------------------------------------------------------------------
extern "C" void kernel_launch(void* const* d_in, const int* in_sizes, int n_in,
                              void* d_out, int out_size) {
    const float* x         = (const float*)d_in[0];
    const float* in_proj_w = (const float*)d_in[1];
    const float* in_proj_b = (const float*)d_in[2];
    const float* out_w     = (const float*)d_in[3];
    const float* out_b     = (const float*)d_in[4];
    float* out = (float*)d_out;

    const int qkv_smem  = 2 * 49152;   // 96KB
    const int outp_smem = 2 * 32768;   // 64KB
    const int attn_smem = 32768 + 2 * 16384;   // 64KB
    cudaFuncSetAttribute(gemm_qkv_tc, cudaFuncAttributeMaxDynamicSharedMemorySize, qkv_smem);
    cudaFuncSetAttribute(gemm_out_tc, cudaFuncAttributeMaxDynamicSharedMemorySize, outp_smem);
    cudaFuncSetAttribute(attn_tc,     cudaFuncAttributeMaxDynamicSharedMemorySize, attn_smem);

    split_weights_kernel<<<(C3 * CCH + 255) / 256, 256>>>(in_proj_w, out_w);
    {
        dim3 grid(CCH / 32, BATCH * HH * 2);
        dim3 blk(32, 8);
        rearrange_kernel<<<grid, blk>>>(x);
    }
    {
        dim3 grid(C3 / 128, MTOT / 64);
        gemm_qkv_tc<<<grid, 256, qkv_smem>>>(in_proj_b);
    }
    attn_tc<<<NPOS * HEADS * 2, 256, attn_smem>>>();
    {
        dim3 grid(CCH / 128, MTOT / 64);
        gemm_out_tc<<<grid, 256, outp_smem>>>(out_b, out);
    }
}